// round 7
// baseline (speedup 1.0000x reference)
#include <cuda_runtime.h>
#include <cuda_fp16.h>
#include <cstdint>

// ---------------- problem constants (capacities) ----------------
#define NMAX   50000
#define EMAX   1600000
#define DH     64
#define NG     64
#define NCLS   10
#define SCAN_B 256

// ---------------- device scratch (no allocations allowed) -------
// Invariant: g_degi, g_pool, g_cnt are ZERO at kernel_launch entry
// (BSS zero-init on first call; restored at the tail of agg_pool / fc).
__device__ __half2 g_Ah1[NMAX * 32];     // ht1 table, fp16 (row = 128B)
__device__ __half2 g_Ah2[NMAX * 32];     // ht2 table, fp16
__device__ float   g_dis[NMAX];          // rsqrt(deg+1)
__device__ int     g_degi[NMAX];         // edge in-degree (no self loop)
__device__ int     g_rowtmp[NMAX];       // per-block exclusive scan
__device__ int     g_bsum[(NMAX + SCAN_B - 1) / SCAN_B];
__device__ int     g_rank[EMAX];         // per-edge rank within its dst row
__device__ int     g_csr[EMAX];          // (src << 7) byte offsets, grouped by dst
__device__ float4  g_pool[NG * 16];      // per-graph feature sums
__device__ float   g_cnt[NG];            // per-graph node counts
__device__ int     g_is32;               // 1 if indices are int32 on the wire

// ---------------- helpers ----------------
__device__ __forceinline__ int load_idx(const void* p, long long i, int is32) {
    if (is32) return ((const int*)p)[i];
    return (int)((const long long*)p)[i];
}

__device__ __forceinline__ void red_add_v4(float* addr, float4 v) {
    asm volatile("red.global.add.v4.f32 [%0], {%1,%2,%3,%4};"
                 :: "l"(addr), "f"(v.x), "f"(v.y), "f"(v.z), "f"(v.w)
                 : "memory");
}

__device__ __forceinline__ void acc_u4(float* acc, uint4 u) {
    float2 f0 = __half22float2(((__half2*)&u)[0]);
    float2 f1 = __half22float2(((__half2*)&u)[1]);
    float2 f2 = __half22float2(((__half2*)&u)[2]);
    float2 f3 = __half22float2(((__half2*)&u)[3]);
    acc[0] += f0.x; acc[1] += f0.y; acc[2] += f1.x; acc[3] += f1.y;
    acc[4] += f2.x; acc[5] += f2.y; acc[6] += f3.x; acc[7] += f3.y;
}

__device__ __forceinline__ uint4 hadd4(uint4 a, uint4 b) {
    uint4 r;
    ((__half2*)&r)[0] = __hadd2(((__half2*)&a)[0], ((__half2*)&b)[0]);
    ((__half2*)&r)[1] = __hadd2(((__half2*)&a)[1], ((__half2*)&b)[1]);
    ((__half2*)&r)[2] = __hadd2(((__half2*)&a)[2], ((__half2*)&b)[2]);
    ((__half2*)&r)[3] = __hadd2(((__half2*)&a)[3], ((__half2*)&b)[3]);
    return r;
}

// virtual rowptr
__device__ __forceinline__ int rowptr_of(int i) {
    return g_rowtmp[i] + g_bsum[i >> 8];
}

// pack 8 floats (scaled by ds) into a uint4 of halves
__device__ __forceinline__ uint4 pack8h(const float* v, float ds) {
    uint4 u;
    ((__half2*)&u)[0] = __floats2half2_rn(v[0] * ds, v[1] * ds);
    ((__half2*)&u)[1] = __floats2half2_rn(v[2] * ds, v[3] * ds);
    ((__half2*)&u)[2] = __floats2half2_rn(v[4] * ds, v[5] * ds);
    ((__half2*)&u)[3] = __floats2half2_rn(v[6] * ds, v[7] * ds);
    return u;
}

__device__ __forceinline__ uint4 gat(const char* base, int off, int l16) {
    return *(const uint4*)(base + off + l16);
}

// ---------------- kernels ----------------

// deg[dst] += 1 over edges, recording per-edge rank. 4 edges/thread.
// Per-block dtype consensus on first 2KB.
__global__ void k_deg(const void* __restrict__ ei, int E) {
    __shared__ int flag;
    if (threadIdx.x == 0) flag = 0;
    __syncthreads();
    long long probe = ((const long long*)ei)[threadIdx.x];
    if ((unsigned long long)probe > 0xFFFFFFFFull) flag = 1;
    __syncthreads();
    int is32 = flag;

    int t = blockIdx.x * blockDim.x + threadIdx.x;
    if (t == 0) g_is32 = is32;
    int e = t * 4;
    if (e >= E) return;

    int d[4], cnt;
    if (is32) {
        const int* dstp = (const int*)ei + E;
        if (e + 3 < E) {
            int4 dv = ((const int4*)dstp)[t];
            d[0] = dv.x; d[1] = dv.y; d[2] = dv.z; d[3] = dv.w; cnt = 4;
        } else {
            cnt = E - e;
            for (int i = 0; i < cnt; i++) d[i] = dstp[e + i];
        }
    } else {
        const long long* dstp = (const long long*)ei + E;
        if (e + 3 < E) {
            longlong2 d0 = ((const longlong2*)dstp)[t * 2];
            longlong2 d1 = ((const longlong2*)dstp)[t * 2 + 1];
            d[0] = (int)d0.x; d[1] = (int)d0.y; d[2] = (int)d1.x; d[3] = (int)d1.y;
            cnt = 4;
        } else {
            cnt = E - e;
            for (int i = 0; i < cnt; i++) d[i] = (int)dstp[e + i];
        }
    }

    if (cnt == 4) {
        int4 r;
        r.x = atomicAdd(&g_degi[d[0]], 1);
        r.y = atomicAdd(&g_degi[d[1]], 1);
        r.z = atomicAdd(&g_degi[d[2]], 1);
        r.w = atomicAdd(&g_degi[d[3]], 1);
        ((int4*)g_rank)[t] = r;
    } else {
        for (int i = 0; i < cnt; i++)
            g_rank[e + i] = atomicAdd(&g_degi[d[i]], 1);
    }
}

// per-block exclusive scan of deg; block sums to g_bsum; dis = rsqrt(deg+1)
__global__ void k_scan1(int n) {
    __shared__ int ws[8];
    int i = blockIdx.x * SCAN_B + threadIdx.x;
    int v = (i < n) ? g_degi[i] : 0;
    int lane = threadIdx.x & 31, w = threadIdx.x >> 5;
    int x = v;
#pragma unroll
    for (int o = 1; o < 32; o <<= 1) {
        int y = __shfl_up_sync(~0u, x, o);
        if (lane >= o) x += y;
    }
    if (lane == 31) ws[w] = x;
    __syncthreads();
    if (w == 0) {
        int y = (lane < 8) ? ws[lane] : 0;
#pragma unroll
        for (int o = 1; o < 8; o <<= 1) {
            int z = __shfl_up_sync(~0u, y, o);
            if (lane >= o) y += z;
        }
        if (lane < 8) ws[lane] = y;
    }
    __syncthreads();
    int incl = x + (w > 0 ? ws[w - 1] : 0);
    if (i < n) {
        g_rowtmp[i] = incl - v;
        g_dis[i] = rsqrtf((float)(v + 1));
    }
    if (threadIdx.x == SCAN_B - 1) g_bsum[blockIdx.x] = incl;
}

// exclusive scan of block sums (nb <= 256), single block
__global__ void k_scan2(int nb) {
    __shared__ int ws[8];
    int lane = threadIdx.x & 31, w = threadIdx.x >> 5;
    int v = (threadIdx.x < nb) ? g_bsum[threadIdx.x] : 0;
    int x = v;
#pragma unroll
    for (int o = 1; o < 32; o <<= 1) {
        int y = __shfl_up_sync(~0u, x, o);
        if (lane >= o) x += y;
    }
    if (lane == 31) ws[w] = x;
    __syncthreads();
    if (w == 0) {
        int y = (lane < 8) ? ws[lane] : 0;
#pragma unroll
        for (int o = 1; o < 8; o <<= 1) {
            int z = __shfl_up_sync(~0u, y, o);
            if (lane >= o) y += z;
        }
        if (lane < 8) ws[lane] = y;
    }
    __syncthreads();
    int excl = x - v + (w > 0 ? ws[w - 1] : 0);
    if (threadIdx.x < nb) g_bsum[threadIdx.x] = excl;
}

// Combined launch: blocks [0, gemmB) do gemm1; blocks [gemmB, ...) do the
// (atomic-free) CSR fill. The two halves touch disjoint pipes (issue/LDS vs L2).
__global__ void k_gemm1_fill(const float* __restrict__ X,
                             const float* __restrict__ W,
                             __half2* __restrict__ ht,
                             const void* __restrict__ ei,
                             int n, int E, int gemmB)
{
    if (blockIdx.x < gemmB) {
        // ---- gemm1: 2 rows per 8-lane group, 64 rows/block ----
        __shared__ float4 Ws4[DH * 16];
        const float4* W4 = (const float4*)W;
        for (int i = threadIdx.x; i < DH * 16; i += blockDim.x) Ws4[i] = W4[i];
        __syncthreads();

        int grp = threadIdx.x >> 3;
        int l   = threadIdx.x & 7;
        int r0  = blockIdx.x * 64 + grp * 2;

        float xr[2][8], acc[2][8];
#pragma unroll
        for (int r = 0; r < 2; r++)
#pragma unroll
            for (int c = 0; c < 8; c++) { acc[r][c] = 0.f; xr[r][c] = 0.f; }

#pragma unroll
        for (int r = 0; r < 2; r++) {
            int row = r0 + r;
            if (row < n) {
                const float4* xp = (const float4*)(X + (size_t)row * DH);
                float4 a = xp[l * 2];
                float4 bq = xp[l * 2 + 1];
                xr[r][0] = a.x;  xr[r][1] = a.y;  xr[r][2] = a.z;  xr[r][3] = a.w;
                xr[r][4] = bq.x; xr[r][5] = bq.y; xr[r][6] = bq.z; xr[r][7] = bq.w;
            }
        }

        for (int kb = 0; kb < 8; kb++) {
#pragma unroll
            for (int j = 0; j < 8; j++) {
                int k = kb * 8 + j;
                float4 w0 = Ws4[k * 16 + l * 2];
                float4 w1 = Ws4[k * 16 + l * 2 + 1];
                float xv0 = __shfl_sync(~0u, xr[0][j], kb, 8);
                float xv1 = __shfl_sync(~0u, xr[1][j], kb, 8);
                acc[0][0] += xv0 * w0.x; acc[0][1] += xv0 * w0.y;
                acc[0][2] += xv0 * w0.z; acc[0][3] += xv0 * w0.w;
                acc[0][4] += xv0 * w1.x; acc[0][5] += xv0 * w1.y;
                acc[0][6] += xv0 * w1.z; acc[0][7] += xv0 * w1.w;
                acc[1][0] += xv1 * w0.x; acc[1][1] += xv1 * w0.y;
                acc[1][2] += xv1 * w0.z; acc[1][3] += xv1 * w0.w;
                acc[1][4] += xv1 * w1.x; acc[1][5] += xv1 * w1.y;
                acc[1][6] += xv1 * w1.z; acc[1][7] += xv1 * w1.w;
            }
        }

#pragma unroll
        for (int r = 0; r < 2; r++) {
            int row = r0 + r;
            if (row < n) {
                float ds = g_dis[row];
                ((uint4*)((__half*)ht + (size_t)row * DH))[l] = pack8h(acc[r], ds);
            }
        }
        return;
    }

    // ---- fill: atomic-free CSR scatter, 4 edges/thread ----
    int t = (blockIdx.x - gemmB) * blockDim.x + threadIdx.x;
    int e = t * 4;
    if (e >= E) return;
    int is32 = g_is32;
    int s[4], d[4], r[4], cnt;
    if (is32) {
        const int* srcp = (const int*)ei;
        const int* dstp = srcp + E;
        if (e + 3 < E) {
            int4 sv = ((const int4*)srcp)[t];
            int4 dv = ((const int4*)dstp)[t];
            int4 rv = ((const int4*)g_rank)[t];
            s[0] = sv.x; s[1] = sv.y; s[2] = sv.z; s[3] = sv.w;
            d[0] = dv.x; d[1] = dv.y; d[2] = dv.z; d[3] = dv.w;
            r[0] = rv.x; r[1] = rv.y; r[2] = rv.z; r[3] = rv.w;
            cnt = 4;
        } else {
            cnt = E - e;
            for (int i = 0; i < cnt; i++) {
                s[i] = srcp[e + i]; d[i] = dstp[e + i]; r[i] = g_rank[e + i];
            }
        }
    } else {
        const long long* srcp = (const long long*)ei;
        const long long* dstp = srcp + E;
        if (e + 3 < E) {
            longlong2 s0 = ((const longlong2*)srcp)[t * 2];
            longlong2 s1 = ((const longlong2*)srcp)[t * 2 + 1];
            longlong2 d0 = ((const longlong2*)dstp)[t * 2];
            longlong2 d1 = ((const longlong2*)dstp)[t * 2 + 1];
            int4 rv = ((const int4*)g_rank)[t];
            s[0] = (int)s0.x; s[1] = (int)s0.y; s[2] = (int)s1.x; s[3] = (int)s1.y;
            d[0] = (int)d0.x; d[1] = (int)d0.y; d[2] = (int)d1.x; d[3] = (int)d1.y;
            r[0] = rv.x; r[1] = rv.y; r[2] = rv.z; r[3] = rv.w;
            cnt = 4;
        } else {
            cnt = E - e;
            for (int i = 0; i < cnt; i++) {
                s[i] = (int)srcp[e + i]; d[i] = (int)dstp[e + i]; r[i] = g_rank[e + i];
            }
        }
    }
#pragma unroll
    for (int i = 0; i < 4; i++) {
        if (i < cnt) {
            int p = rowptr_of(d[i]) + r[i];
            g_csr[p] = s[i] << 7;
        }
    }
}

// shared gather-sum: fp32 acc[8] = sum of ht rows (self + neighbors)
__device__ __forceinline__ void gather_sum(const __half2* __restrict__ ht,
                                           int node, int l, float* acc)
{
    const char* hb = (const char*)ht;
    int l16 = l << 4;
#pragma unroll
    for (int j = 0; j < 8; j++) acc[j] = 0.f;
    acc_u4(acc, gat(hb, node << 7, l16));   // self loop

    int k = rowptr_of(node);
    int e = k + g_degi[node];
    for (; k + 8 <= e; k += 8) {
        int o0 = g_csr[k],     o1 = g_csr[k + 1];
        int o2 = g_csr[k + 2], o3 = g_csr[k + 3];
        int o4 = g_csr[k + 4], o5 = g_csr[k + 5];
        int o6 = g_csr[k + 6], o7 = g_csr[k + 7];
        uint4 v0 = gat(hb, o0, l16), v1 = gat(hb, o1, l16);
        uint4 v2 = gat(hb, o2, l16), v3 = gat(hb, o3, l16);
        uint4 v4 = gat(hb, o4, l16), v5 = gat(hb, o5, l16);
        uint4 v6 = gat(hb, o6, l16), v7 = gat(hb, o7, l16);
        uint4 t0 = hadd4(hadd4(v0, v1), hadd4(v2, v3));
        uint4 t1 = hadd4(hadd4(v4, v5), hadd4(v6, v7));
        acc_u4(acc, hadd4(t0, t1));
    }
    for (; k + 4 <= e; k += 4) {
        int o0 = g_csr[k],     o1 = g_csr[k + 1];
        int o2 = g_csr[k + 2], o3 = g_csr[k + 3];
        uint4 v0 = gat(hb, o0, l16), v1 = gat(hb, o1, l16);
        uint4 v2 = gat(hb, o2, l16), v3 = gat(hb, o3, l16);
        acc_u4(acc, hadd4(hadd4(v0, v1), hadd4(v2, v3)));
    }
    for (; k < e; k++) acc_u4(acc, gat(hb, g_csr[k], l16));
}

// Fused: agg over ht1 -> h1 (regs) -> gemv W2 (fp16 hfma2) -> ht2 (fp16).
__global__ void k_agg1_gemm2(const __half2* __restrict__ ht1,
                             const float* __restrict__ b,
                             const float* __restrict__ W2,
                             __half2* __restrict__ ht2, int n)
{
    __shared__ uint4 W2h[DH * 8];   // W2[64][64] fp16, 8KB
    {
        const float4* w4 = (const float4*)W2;
        for (int i = threadIdx.x; i < DH * 8; i += blockDim.x) {
            float4 a = w4[i * 2], c = w4[i * 2 + 1];
            uint4 u;
            ((__half2*)&u)[0] = __floats2half2_rn(a.x, a.y);
            ((__half2*)&u)[1] = __floats2half2_rn(a.z, a.w);
            ((__half2*)&u)[2] = __floats2half2_rn(c.x, c.y);
            ((__half2*)&u)[3] = __floats2half2_rn(c.z, c.w);
            W2h[i] = u;
        }
    }
    __syncthreads();

    int node = blockIdx.x * 32 + (threadIdx.x >> 3);
    int l = threadIdx.x & 7;

    float hv[8];
#pragma unroll
    for (int j = 0; j < 8; j++) hv[j] = 0.f;

    if (node < n) {
        float acc[8];
        gather_sum(ht1, node, l, acc);
        float ds = g_dis[node];
        const float4* b4 = (const float4*)b;
        float4 b0 = b4[l * 2], b1 = b4[l * 2 + 1];
        hv[0] = fmaxf(acc[0] * ds + b0.x, 0.f);
        hv[1] = fmaxf(acc[1] * ds + b0.y, 0.f);
        hv[2] = fmaxf(acc[2] * ds + b0.z, 0.f);
        hv[3] = fmaxf(acc[3] * ds + b0.w, 0.f);
        hv[4] = fmaxf(acc[4] * ds + b1.x, 0.f);
        hv[5] = fmaxf(acc[5] * ds + b1.y, 0.f);
        hv[6] = fmaxf(acc[6] * ds + b1.z, 0.f);
        hv[7] = fmaxf(acc[7] * ds + b1.w, 0.f);
    }

    __half2 accA[4], accB[4];
    __half2 z = __floats2half2_rn(0.f, 0.f);
#pragma unroll
    for (int i = 0; i < 4; i++) { accA[i] = z; accB[i] = z; }

    for (int kb = 0; kb < 8; kb++) {
#pragma unroll
        for (int j = 0; j < 8; j++) {
            float xs = __shfl_sync(~0u, hv[j], kb, 8);
            __half2 xs2 = __floats2half2_rn(xs, xs);
            uint4 wv = W2h[(kb * 8 + j) * 8 + l];
            __half2* wh = (__half2*)&wv;
            if (j & 1) {
#pragma unroll
                for (int i = 0; i < 4; i++) accB[i] = __hfma2(wh[i], xs2, accB[i]);
            } else {
#pragma unroll
                for (int i = 0; i < 4; i++) accA[i] = __hfma2(wh[i], xs2, accA[i]);
            }
        }
    }

    if (node < n) {
        float ga[8];
#pragma unroll
        for (int i = 0; i < 4; i++) {
            float2 fa = __half22float2(accA[i]);
            float2 fb = __half22float2(accB[i]);
            ga[2 * i]     = fa.x + fb.x;
            ga[2 * i + 1] = fa.y + fb.y;
        }
        float ds = g_dis[node];
        ((uint4*)((__half*)ht2 + (size_t)node * DH))[l] = pack8h(ga, ds);
    }
}

// Aggregate layer 2 + pool atomics; restores degi to zero.
__global__ void k_agg_pool(const __half2* __restrict__ ht,
                           const float* __restrict__ b,
                           const void* __restrict__ batch, int n)
{
    int t = blockIdx.x * blockDim.x + threadIdx.x;
    int node = t >> 3;
    if (node >= n) return;
    int l = t & 7;

    float acc[8];
    gather_sum(ht, node, l, acc);

    float ds = g_dis[node];
    const float4* b4 = (const float4*)b;
    float4 b0 = b4[l * 2], b1 = b4[l * 2 + 1];
    float4 r0, r1;
    r0.x = fmaxf(acc[0] * ds + b0.x, 0.f);
    r0.y = fmaxf(acc[1] * ds + b0.y, 0.f);
    r0.z = fmaxf(acc[2] * ds + b0.z, 0.f);
    r0.w = fmaxf(acc[3] * ds + b0.w, 0.f);
    r1.x = fmaxf(acc[4] * ds + b1.x, 0.f);
    r1.y = fmaxf(acc[5] * ds + b1.y, 0.f);
    r1.z = fmaxf(acc[6] * ds + b1.z, 0.f);
    r1.w = fmaxf(acc[7] * ds + b1.w, 0.f);

    int gph = load_idx(batch, node, g_is32);
    float* pp = (float*)g_pool + (size_t)gph * DH + l * 8;
    red_add_v4(pp, r0);
    red_add_v4(pp + 4, r1);
    if (l == 0) {
        atomicAdd(&g_cnt[gph], 1.0f);
        g_degi[node] = 0;    // restore zero-state for next launch
    }
}

// out = (pool / max(cnt,1)) @ Wfc + bfc; restores pool/cnt to zero.
__global__ void k_fc(const float* __restrict__ Wfc, const float* __restrict__ bfc,
                     float* __restrict__ out)
{
    int t = threadIdx.x;
    int gph = t / NCLS, c = t % NCLS;
    float inv = 1.0f / fmaxf(g_cnt[gph], 1.0f);
    const float* pr = (const float*)g_pool + (size_t)gph * DH;
    float acc = 0.f;
#pragma unroll
    for (int j = 0; j < DH; j++) acc += pr[j] * Wfc[j * NCLS + c];
    out[t] = acc * inv + bfc[c];

    __syncthreads();
    for (int i = t; i < NG * 16; i += blockDim.x)
        g_pool[i] = make_float4(0.f, 0.f, 0.f, 0.f);
    if (t < NG) g_cnt[t] = 0.0f;
}

// ---------------- launcher ----------------
extern "C" void kernel_launch(void* const* d_in, const int* in_sizes, int n_in,
                              void* d_out, int out_size)
{
    const float* x   = (const float*)d_in[0];
    const void*  ei  = d_in[1];
    const void*  bat = d_in[2];
    const float* W1  = (const float*)d_in[3];
    const float* b1  = (const float*)d_in[4];
    const float* W2  = (const float*)d_in[5];
    const float* b2  = (const float*)d_in[6];
    const float* Wfc = (const float*)d_in[7];
    const float* bfc = (const float*)d_in[8];
    float* out = (float*)d_out;

    int n = in_sizes[0] / DH;       // nodes
    int E = in_sizes[1] / 2;        // edges

    static __half2* pA1 = nullptr; static __half2* pA2 = nullptr;
    if (!pA1) {
        void* tmp;
        cudaGetSymbolAddress(&tmp, g_Ah1); pA1 = (__half2*)tmp;
        cudaGetSymbolAddress(&tmp, g_Ah2); pA2 = (__half2*)tmp;
    }

    const int TB = 256;
    int nb_scan = (n + SCAN_B - 1) / SCAN_B;
    int q_e_blocks = ((E + 3) / 4 + TB - 1) / TB;
    int gemm_blocks = (n + 63) / 64;
    int fused_blocks = (n + 31) / 32;
    int agg_blocks = ((long long)n * 8 + TB - 1) / TB;

    k_deg<<<q_e_blocks, TB>>>(ei, E);                                   // 1
    k_scan1<<<nb_scan, SCAN_B>>>(n);                                    // 2
    k_scan2<<<1, SCAN_B>>>(nb_scan);                                    // 3
    k_gemm1_fill<<<gemm_blocks + q_e_blocks, TB>>>(x, W1, pA1, ei,
                                                   n, E, gemm_blocks);  // 4 (profiled)
    k_agg1_gemm2<<<fused_blocks, TB>>>(pA1, b1, W2, pA2, n);            // 5
    k_agg_pool<<<agg_blocks, TB>>>(pA2, b2, bat, n);                    // 6
    k_fc<<<1, NG * NCLS>>>(Wfc, bfc, out);                              // 7
}

// round 8
// speedup vs baseline: 1.0438x; 1.0438x over previous
#include <cuda_runtime.h>
#include <cuda_fp16.h>
#include <cstdint>

// ---------------- problem constants (capacities) ----------------
#define NMAX   50000
#define EMAX   1600000
#define DH     64
#define NG     64
#define NCLS   10
#define SCAN_B 256

// ---------------- device scratch (no allocations allowed) -------
// Invariant at kernel_launch entry (BSS zero-init on first call, restored
// at the tail of consumers every call): g_degi=0, g_pool=0, g_cnt=0,
// g_ctr_scan=0, g_ctr_pool=0.
__device__ __half2 g_Ah1[NMAX * 32];     // ht1 table, fp16 (row = 128B)
__device__ __half2 g_Ah2[NMAX * 32];     // ht2 table, fp16
__device__ float   g_dis[NMAX];          // rsqrt(deg+1)
__device__ int     g_degi[NMAX];         // edge in-degree (no self loop)
__device__ int     g_rowtmp[NMAX];       // per-block exclusive scan
__device__ int     g_bsum[(NMAX + SCAN_B - 1) / SCAN_B];
__device__ int     g_rank[EMAX];         // per-edge rank within its dst row
__device__ int     g_csr[EMAX];          // (src << 7) byte offsets, grouped by dst
__device__ float4  g_pool[NG * 16];      // per-graph feature sums
__device__ float   g_cnt[NG];            // per-graph node counts
__device__ int     g_is32;               // 1 if indices are int32 on the wire
__device__ int     g_ctr_scan;           // last-block counter for scan
__device__ int     g_ctr_pool;           // last-block counter for pool->fc

// ---------------- helpers ----------------
__device__ __forceinline__ int load_idx(const void* p, long long i, int is32) {
    if (is32) return ((const int*)p)[i];
    return (int)((const long long*)p)[i];
}

__device__ __forceinline__ void red_add_v4(float* addr, float4 v) {
    asm volatile("red.global.add.v4.f32 [%0], {%1,%2,%3,%4};"
                 :: "l"(addr), "f"(v.x), "f"(v.y), "f"(v.z), "f"(v.w)
                 : "memory");
}

__device__ __forceinline__ void acc_u4(float* acc, uint4 u) {
    float2 f0 = __half22float2(((__half2*)&u)[0]);
    float2 f1 = __half22float2(((__half2*)&u)[1]);
    float2 f2 = __half22float2(((__half2*)&u)[2]);
    float2 f3 = __half22float2(((__half2*)&u)[3]);
    acc[0] += f0.x; acc[1] += f0.y; acc[2] += f1.x; acc[3] += f1.y;
    acc[4] += f2.x; acc[5] += f2.y; acc[6] += f3.x; acc[7] += f3.y;
}

__device__ __forceinline__ uint4 hadd4(uint4 a, uint4 b) {
    uint4 r;
    ((__half2*)&r)[0] = __hadd2(((__half2*)&a)[0], ((__half2*)&b)[0]);
    ((__half2*)&r)[1] = __hadd2(((__half2*)&a)[1], ((__half2*)&b)[1]);
    ((__half2*)&r)[2] = __hadd2(((__half2*)&a)[2], ((__half2*)&b)[2]);
    ((__half2*)&r)[3] = __hadd2(((__half2*)&a)[3], ((__half2*)&b)[3]);
    return r;
}

__device__ __forceinline__ int rowptr_of(int i) {
    return g_rowtmp[i] + g_bsum[i >> 8];
}

__device__ __forceinline__ uint4 pack8h(const float* v, float ds) {
    uint4 u;
    ((__half2*)&u)[0] = __floats2half2_rn(v[0] * ds, v[1] * ds);
    ((__half2*)&u)[1] = __floats2half2_rn(v[2] * ds, v[3] * ds);
    ((__half2*)&u)[2] = __floats2half2_rn(v[4] * ds, v[5] * ds);
    ((__half2*)&u)[3] = __floats2half2_rn(v[6] * ds, v[7] * ds);
    return u;
}

__device__ __forceinline__ uint4 gat(const char* base, int off, int l16) {
    return *(const uint4*)(base + off + l16);
}

// stage a fp32 64x64 weight matrix into fp16 smem (uint4 per 8 cols)
__device__ __forceinline__ void stage_w_h(const float* __restrict__ W, uint4* Wh) {
    const float4* w4 = (const float4*)W;
    for (int i = threadIdx.x; i < DH * 8; i += blockDim.x) {
        float4 a = w4[i * 2], c = w4[i * 2 + 1];
        uint4 u;
        ((__half2*)&u)[0] = __floats2half2_rn(a.x, a.y);
        ((__half2*)&u)[1] = __floats2half2_rn(a.z, a.w);
        ((__half2*)&u)[2] = __floats2half2_rn(c.x, c.y);
        ((__half2*)&u)[3] = __floats2half2_rn(c.z, c.w);
        Wh[i] = u;
    }
}

// ---------------- kernels ----------------

// deg[dst] += 1 over edges, recording per-edge rank. 4 edges/thread.
__global__ void k_deg(const void* __restrict__ ei, int E) {
    __shared__ int flag;
    if (threadIdx.x == 0) flag = 0;
    __syncthreads();
    long long probe = ((const long long*)ei)[threadIdx.x];
    if ((unsigned long long)probe > 0xFFFFFFFFull) flag = 1;
    __syncthreads();
    int is32 = flag;

    int t = blockIdx.x * blockDim.x + threadIdx.x;
    if (t == 0) g_is32 = is32;
    int e = t * 4;
    if (e >= E) return;

    int d[4], cnt;
    if (is32) {
        const int* dstp = (const int*)ei + E;
        if (e + 3 < E) {
            int4 dv = ((const int4*)dstp)[t];
            d[0] = dv.x; d[1] = dv.y; d[2] = dv.z; d[3] = dv.w; cnt = 4;
        } else {
            cnt = E - e;
            for (int i = 0; i < cnt; i++) d[i] = dstp[e + i];
        }
    } else {
        const long long* dstp = (const long long*)ei + E;
        if (e + 3 < E) {
            longlong2 d0 = ((const longlong2*)dstp)[t * 2];
            longlong2 d1 = ((const longlong2*)dstp)[t * 2 + 1];
            d[0] = (int)d0.x; d[1] = (int)d0.y; d[2] = (int)d1.x; d[3] = (int)d1.y;
            cnt = 4;
        } else {
            cnt = E - e;
            for (int i = 0; i < cnt; i++) d[i] = (int)dstp[e + i];
        }
    }

    if (cnt == 4) {
        int4 r;
        r.x = atomicAdd(&g_degi[d[0]], 1);
        r.y = atomicAdd(&g_degi[d[1]], 1);
        r.z = atomicAdd(&g_degi[d[2]], 1);
        r.w = atomicAdd(&g_degi[d[3]], 1);
        ((int4*)g_rank)[t] = r;
    } else {
        for (int i = 0; i < cnt; i++)
            g_rank[e + i] = atomicAdd(&g_degi[d[i]], 1);
    }
}

// Fused scan: per-block exclusive scan + dis, then the LAST block scans
// the block sums (classic threadfence-reduction pattern).
__global__ void k_scan(int n) {
    __shared__ int ws[8];
    __shared__ int isLast;
    int i = blockIdx.x * SCAN_B + threadIdx.x;
    int v = (i < n) ? g_degi[i] : 0;
    int lane = threadIdx.x & 31, w = threadIdx.x >> 5;
    int x = v;
#pragma unroll
    for (int o = 1; o < 32; o <<= 1) {
        int y = __shfl_up_sync(~0u, x, o);
        if (lane >= o) x += y;
    }
    if (lane == 31) ws[w] = x;
    __syncthreads();
    if (w == 0) {
        int y = (lane < 8) ? ws[lane] : 0;
#pragma unroll
        for (int o = 1; o < 8; o <<= 1) {
            int z = __shfl_up_sync(~0u, y, o);
            if (lane >= o) y += z;
        }
        if (lane < 8) ws[lane] = y;
    }
    __syncthreads();
    int incl = x + (w > 0 ? ws[w - 1] : 0);
    if (i < n) {
        g_rowtmp[i] = incl - v;
        g_dis[i] = rsqrtf((float)(v + 1));
    }
    if (threadIdx.x == SCAN_B - 1) g_bsum[blockIdx.x] = incl;

    // ---- last-block election ----
    __threadfence();
    if (threadIdx.x == 0) {
        int d = atomicAdd(&g_ctr_scan, 1);
        isLast = (d == (int)gridDim.x - 1);
        if (isLast) g_ctr_scan = 0;          // restore invariant
    }
    __syncthreads();
    if (!isLast) return;

    // exclusive scan of block sums (gridDim.x <= 256)
    int nb = gridDim.x;
    int v2 = (threadIdx.x < nb) ? g_bsum[threadIdx.x] : 0;
    int x2 = v2;
#pragma unroll
    for (int o = 1; o < 32; o <<= 1) {
        int y = __shfl_up_sync(~0u, x2, o);
        if (lane >= o) x2 += y;
    }
    __syncthreads();
    if (lane == 31) ws[w] = x2;
    __syncthreads();
    if (w == 0) {
        int y = (lane < 8) ? ws[lane] : 0;
#pragma unroll
        for (int o = 1; o < 8; o <<= 1) {
            int z = __shfl_up_sync(~0u, y, o);
            if (lane >= o) y += z;
        }
        if (lane < 8) ws[lane] = y;
    }
    __syncthreads();
    int excl = x2 - v2 + (w > 0 ? ws[w - 1] : 0);
    if (threadIdx.x < nb) g_bsum[threadIdx.x] = excl;
}

// Combined: blocks [0, gemmB) do gemm1 (fp16 hfma2); rest do atomic-free fill.
__global__ void k_gemm1_fill(const float* __restrict__ X,
                             const float* __restrict__ W,
                             __half2* __restrict__ ht,
                             const void* __restrict__ ei,
                             int n, int E, int gemmB)
{
    if (blockIdx.x < gemmB) {
        __shared__ uint4 W1h[DH * 8];    // W1 fp16, 8KB
        stage_w_h(W, W1h);
        __syncthreads();

        int grp = threadIdx.x >> 3;
        int l   = threadIdx.x & 7;
        int r0  = blockIdx.x * 64 + grp * 2;

        float xr[2][8];
#pragma unroll
        for (int r = 0; r < 2; r++)
#pragma unroll
            for (int c = 0; c < 8; c++) xr[r][c] = 0.f;

#pragma unroll
        for (int r = 0; r < 2; r++) {
            int row = r0 + r;
            if (row < n) {
                const float4* xp = (const float4*)(X + (size_t)row * DH);
                float4 a = xp[l * 2];
                float4 bq = xp[l * 2 + 1];
                xr[r][0] = a.x;  xr[r][1] = a.y;  xr[r][2] = a.z;  xr[r][3] = a.w;
                xr[r][4] = bq.x; xr[r][5] = bq.y; xr[r][6] = bq.z; xr[r][7] = bq.w;
            }
        }

        __half2 z = __floats2half2_rn(0.f, 0.f);
        __half2 aA0[4], aB0[4], aA1[4], aB1[4];
#pragma unroll
        for (int i = 0; i < 4; i++) { aA0[i] = z; aB0[i] = z; aA1[i] = z; aB1[i] = z; }

        for (int kb = 0; kb < 8; kb++) {
#pragma unroll
            for (int j = 0; j < 8; j++) {
                float xs0 = __shfl_sync(~0u, xr[0][j], kb, 8);
                float xs1 = __shfl_sync(~0u, xr[1][j], kb, 8);
                __half2 h0 = __floats2half2_rn(xs0, xs0);
                __half2 h1 = __floats2half2_rn(xs1, xs1);
                uint4 wv = W1h[(kb * 8 + j) * 8 + l];
                __half2* wh = (__half2*)&wv;
                if (j & 1) {
#pragma unroll
                    for (int i = 0; i < 4; i++) {
                        aB0[i] = __hfma2(wh[i], h0, aB0[i]);
                        aB1[i] = __hfma2(wh[i], h1, aB1[i]);
                    }
                } else {
#pragma unroll
                    for (int i = 0; i < 4; i++) {
                        aA0[i] = __hfma2(wh[i], h0, aA0[i]);
                        aA1[i] = __hfma2(wh[i], h1, aA1[i]);
                    }
                }
            }
        }

#pragma unroll
        for (int r = 0; r < 2; r++) {
            int row = r0 + r;
            if (row < n) {
                float ga[8];
                __half2* pa = (r == 0) ? aA0 : aA1;
                __half2* pb = (r == 0) ? aB0 : aB1;
#pragma unroll
                for (int i = 0; i < 4; i++) {
                    float2 fa = __half22float2(pa[i]);
                    float2 fb = __half22float2(pb[i]);
                    ga[2 * i]     = fa.x + fb.x;
                    ga[2 * i + 1] = fa.y + fb.y;
                }
                float ds = g_dis[row];
                ((uint4*)((__half*)ht + (size_t)row * DH))[l] = pack8h(ga, ds);
            }
        }
        return;
    }

    // ---- fill: atomic-free CSR scatter, 4 edges/thread ----
    int t = (blockIdx.x - gemmB) * blockDim.x + threadIdx.x;
    int e = t * 4;
    if (e >= E) return;
    int is32 = g_is32;
    int s[4], d[4], r[4], cnt;
    if (is32) {
        const int* srcp = (const int*)ei;
        const int* dstp = srcp + E;
        if (e + 3 < E) {
            int4 sv = ((const int4*)srcp)[t];
            int4 dv = ((const int4*)dstp)[t];
            int4 rv = ((const int4*)g_rank)[t];
            s[0] = sv.x; s[1] = sv.y; s[2] = sv.z; s[3] = sv.w;
            d[0] = dv.x; d[1] = dv.y; d[2] = dv.z; d[3] = dv.w;
            r[0] = rv.x; r[1] = rv.y; r[2] = rv.z; r[3] = rv.w;
            cnt = 4;
        } else {
            cnt = E - e;
            for (int i = 0; i < cnt; i++) {
                s[i] = srcp[e + i]; d[i] = dstp[e + i]; r[i] = g_rank[e + i];
            }
        }
    } else {
        const long long* srcp = (const long long*)ei;
        const long long* dstp = srcp + E;
        if (e + 3 < E) {
            longlong2 s0 = ((const longlong2*)srcp)[t * 2];
            longlong2 s1 = ((const longlong2*)srcp)[t * 2 + 1];
            longlong2 d0 = ((const longlong2*)dstp)[t * 2];
            longlong2 d1 = ((const longlong2*)dstp)[t * 2 + 1];
            int4 rv = ((const int4*)g_rank)[t];
            s[0] = (int)s0.x; s[1] = (int)s0.y; s[2] = (int)s1.x; s[3] = (int)s1.y;
            d[0] = (int)d0.x; d[1] = (int)d0.y; d[2] = (int)d1.x; d[3] = (int)d1.y;
            r[0] = rv.x; r[1] = rv.y; r[2] = rv.z; r[3] = rv.w;
            cnt = 4;
        } else {
            cnt = E - e;
            for (int i = 0; i < cnt; i++) {
                s[i] = (int)srcp[e + i]; d[i] = (int)dstp[e + i]; r[i] = g_rank[e + i];
            }
        }
    }
#pragma unroll
    for (int i = 0; i < 4; i++) {
        if (i < cnt) {
            int p = rowptr_of(d[i]) + r[i];
            g_csr[p] = s[i] << 7;
        }
    }
}

// shared gather-sum: fp32 acc[8] = sum of ht rows (self + neighbors)
__device__ __forceinline__ void gather_sum(const __half2* __restrict__ ht,
                                           int node, int l, float* acc)
{
    const char* hb = (const char*)ht;
    int l16 = l << 4;
#pragma unroll
    for (int j = 0; j < 8; j++) acc[j] = 0.f;
    acc_u4(acc, gat(hb, node << 7, l16));   // self loop

    int k = rowptr_of(node);
    int e = k + g_degi[node];
    for (; k + 8 <= e; k += 8) {
        int o0 = g_csr[k],     o1 = g_csr[k + 1];
        int o2 = g_csr[k + 2], o3 = g_csr[k + 3];
        int o4 = g_csr[k + 4], o5 = g_csr[k + 5];
        int o6 = g_csr[k + 6], o7 = g_csr[k + 7];
        uint4 v0 = gat(hb, o0, l16), v1 = gat(hb, o1, l16);
        uint4 v2 = gat(hb, o2, l16), v3 = gat(hb, o3, l16);
        uint4 v4 = gat(hb, o4, l16), v5 = gat(hb, o5, l16);
        uint4 v6 = gat(hb, o6, l16), v7 = gat(hb, o7, l16);
        uint4 t0 = hadd4(hadd4(v0, v1), hadd4(v2, v3));
        uint4 t1 = hadd4(hadd4(v4, v5), hadd4(v6, v7));
        acc_u4(acc, hadd4(t0, t1));
    }
    for (; k + 4 <= e; k += 4) {
        int o0 = g_csr[k],     o1 = g_csr[k + 1];
        int o2 = g_csr[k + 2], o3 = g_csr[k + 3];
        uint4 v0 = gat(hb, o0, l16), v1 = gat(hb, o1, l16);
        uint4 v2 = gat(hb, o2, l16), v3 = gat(hb, o3, l16);
        acc_u4(acc, hadd4(hadd4(v0, v1), hadd4(v2, v3)));
    }
    for (; k < e; k++) acc_u4(acc, gat(hb, g_csr[k], l16));
}

// Fused: agg over ht1 -> h1 (regs) -> gemv W2 (fp16 hfma2) -> ht2 (fp16).
__global__ void k_agg1_gemm2(const __half2* __restrict__ ht1,
                             const float* __restrict__ b,
                             const float* __restrict__ W2,
                             __half2* __restrict__ ht2, int n)
{
    __shared__ uint4 W2h[DH * 8];
    stage_w_h(W2, W2h);
    __syncthreads();

    int node = blockIdx.x * 32 + (threadIdx.x >> 3);
    int l = threadIdx.x & 7;

    float hv[8];
#pragma unroll
    for (int j = 0; j < 8; j++) hv[j] = 0.f;

    if (node < n) {
        float acc[8];
        gather_sum(ht1, node, l, acc);
        float ds = g_dis[node];
        const float4* b4 = (const float4*)b;
        float4 b0 = b4[l * 2], b1 = b4[l * 2 + 1];
        hv[0] = fmaxf(acc[0] * ds + b0.x, 0.f);
        hv[1] = fmaxf(acc[1] * ds + b0.y, 0.f);
        hv[2] = fmaxf(acc[2] * ds + b0.z, 0.f);
        hv[3] = fmaxf(acc[3] * ds + b0.w, 0.f);
        hv[4] = fmaxf(acc[4] * ds + b1.x, 0.f);
        hv[5] = fmaxf(acc[5] * ds + b1.y, 0.f);
        hv[6] = fmaxf(acc[6] * ds + b1.z, 0.f);
        hv[7] = fmaxf(acc[7] * ds + b1.w, 0.f);
    }

    __half2 accA[4], accB[4];
    __half2 z = __floats2half2_rn(0.f, 0.f);
#pragma unroll
    for (int i = 0; i < 4; i++) { accA[i] = z; accB[i] = z; }

    for (int kb = 0; kb < 8; kb++) {
#pragma unroll
        for (int j = 0; j < 8; j++) {
            float xs = __shfl_sync(~0u, hv[j], kb, 8);
            __half2 xs2 = __floats2half2_rn(xs, xs);
            uint4 wv = W2h[(kb * 8 + j) * 8 + l];
            __half2* wh = (__half2*)&wv;
            if (j & 1) {
#pragma unroll
                for (int i = 0; i < 4; i++) accB[i] = __hfma2(wh[i], xs2, accB[i]);
            } else {
#pragma unroll
                for (int i = 0; i < 4; i++) accA[i] = __hfma2(wh[i], xs2, accA[i]);
            }
        }
    }

    if (node < n) {
        float ga[8];
#pragma unroll
        for (int i = 0; i < 4; i++) {
            float2 fa = __half22float2(accA[i]);
            float2 fb = __half22float2(accB[i]);
            ga[2 * i]     = fa.x + fb.x;
            ga[2 * i + 1] = fa.y + fb.y;
        }
        float ds = g_dis[node];
        ((uint4*)((__half*)ht2 + (size_t)node * DH))[l] = pack8h(ga, ds);
    }
}

// Aggregate layer 2 + pool atomics; LAST block computes the FC and
// restores pool/cnt. Also restores degi per node.
__global__ void k_agg_pool_fc(const __half2* __restrict__ ht,
                              const float* __restrict__ b,
                              const void* __restrict__ batch,
                              const float* __restrict__ Wfc,
                              const float* __restrict__ bfc,
                              float* __restrict__ out, int n)
{
    int t = blockIdx.x * blockDim.x + threadIdx.x;
    int node = t >> 3;
    int l = t & 7;

    if (node < n) {
        float acc[8];
        gather_sum(ht, node, l, acc);

        float ds = g_dis[node];
        const float4* b4 = (const float4*)b;
        float4 b0 = b4[l * 2], b1 = b4[l * 2 + 1];
        float4 r0, r1;
        r0.x = fmaxf(acc[0] * ds + b0.x, 0.f);
        r0.y = fmaxf(acc[1] * ds + b0.y, 0.f);
        r0.z = fmaxf(acc[2] * ds + b0.z, 0.f);
        r0.w = fmaxf(acc[3] * ds + b0.w, 0.f);
        r1.x = fmaxf(acc[4] * ds + b1.x, 0.f);
        r1.y = fmaxf(acc[5] * ds + b1.y, 0.f);
        r1.z = fmaxf(acc[6] * ds + b1.z, 0.f);
        r1.w = fmaxf(acc[7] * ds + b1.w, 0.f);

        int gph = load_idx(batch, node, g_is32);
        float* pp = (float*)g_pool + (size_t)gph * DH + l * 8;
        red_add_v4(pp, r0);
        red_add_v4(pp + 4, r1);
        if (l == 0) {
            atomicAdd(&g_cnt[gph], 1.0f);
            g_degi[node] = 0;    // restore zero-state for next replay
        }
    }

    // ---- last-block election, then FC ----
    __threadfence();
    __shared__ int isLast;
    if (threadIdx.x == 0) {
        int d = atomicAdd(&g_ctr_pool, 1);
        isLast = (d == (int)gridDim.x - 1);
        if (isLast) g_ctr_pool = 0;          // restore invariant
    }
    __syncthreads();
    if (!isLast) return;

    for (int i = threadIdx.x; i < NG * NCLS; i += blockDim.x) {
        int gph = i / NCLS, c = i % NCLS;
        float inv = 1.0f / fmaxf(g_cnt[gph], 1.0f);
        const float* pr = (const float*)g_pool + (size_t)gph * DH;
        float acc = 0.f;
#pragma unroll
        for (int j = 0; j < DH; j++) acc += pr[j] * Wfc[j * NCLS + c];
        out[i] = acc * inv + bfc[c];
    }
    __syncthreads();
    for (int i = threadIdx.x; i < NG * 16; i += blockDim.x)
        g_pool[i] = make_float4(0.f, 0.f, 0.f, 0.f);
    if (threadIdx.x < NG) g_cnt[threadIdx.x] = 0.0f;
}

// ---------------- launcher ----------------
extern "C" void kernel_launch(void* const* d_in, const int* in_sizes, int n_in,
                              void* d_out, int out_size)
{
    const float* x   = (const float*)d_in[0];
    const void*  ei  = d_in[1];
    const void*  bat = d_in[2];
    const float* W1  = (const float*)d_in[3];
    const float* b1  = (const float*)d_in[4];
    const float* W2  = (const float*)d_in[5];
    const float* b2  = (const float*)d_in[6];
    const float* Wfc = (const float*)d_in[7];
    const float* bfc = (const float*)d_in[8];
    float* out = (float*)d_out;

    int n = in_sizes[0] / DH;       // nodes
    int E = in_sizes[1] / 2;        // edges

    static __half2* pA1 = nullptr; static __half2* pA2 = nullptr;
    if (!pA1) {
        void* tmp;
        cudaGetSymbolAddress(&tmp, g_Ah1); pA1 = (__half2*)tmp;
        cudaGetSymbolAddress(&tmp, g_Ah2); pA2 = (__half2*)tmp;
    }

    const int TB = 256;
    int nb_scan = (n + SCAN_B - 1) / SCAN_B;
    int q_e_blocks = ((E + 3) / 4 + TB - 1) / TB;
    int gemm_blocks = (n + 63) / 64;
    int fused_blocks = (n + 31) / 32;
    int agg_blocks = ((long long)n * 8 + TB - 1) / TB;

    k_deg<<<q_e_blocks, TB>>>(ei, E);                                   // 1
    k_scan<<<nb_scan, SCAN_B>>>(n);                                     // 2
    k_gemm1_fill<<<gemm_blocks + q_e_blocks, TB>>>(x, W1, pA1, ei,
                                                   n, E, gemm_blocks);  // 3
    k_agg1_gemm2<<<fused_blocks, TB>>>(pA1, b1, W2, pA2, n);            // 4
    k_agg_pool_fc<<<agg_blocks, TB>>>(pA2, b2, bat, Wfc, bfc, out, n);  // 5
}